// round 7
// baseline (speedup 1.0000x reference)
#include <cuda_runtime.h>
#include <cstdint>

typedef unsigned long long ull;

// ---- packed f32x2 helpers: per-lane IEEE fp32 semantics ----
__device__ __forceinline__ ull fma2(ull a, ull b, ull c) {
    ull d;
    asm("fma.rn.f32x2 %0, %1, %2, %3;" : "=l"(d) : "l"(a), "l"(b), "l"(c));
    return d;
}
__device__ __forceinline__ ull add2(ull a, ull b) {
    ull d;
    asm("add.rn.f32x2 %0, %1, %2;" : "=l"(d) : "l"(a), "l"(b));
    return d;
}
__device__ __forceinline__ float ulo(ull v) { return __uint_as_float((unsigned)v); }
__device__ __forceinline__ float uhi(ull v) { return __uint_as_float((unsigned)(v >> 32)); }
__device__ __forceinline__ ull dup2a(float x) {
    ull d;
    asm("mov.b64 %0, {%1, %1};" : "=l"(d) : "f"(x));
    return d;
}
__device__ __forceinline__ ull dup2(float x) {
    unsigned u = __float_as_uint(x);
    return ((ull)u << 32) | (ull)u;
}

static constexpr int D       = 64;
static constexpr int HW      = 4096;
static constexpr int K       = 512;
static constexpr int N_VEC   = 131072;
static constexpr int N_ELEMS = N_VEC * D;         // 8388608
static constexpr int LOSS_OFF = N_ELEMS;
static constexpr int IDX_OFF  = N_ELEMS + 1;
static constexpr int THREADS  = 512;
static constexpr int NCTA     = 148;
static constexpr int VTILE    = 128;              // vectors per CTA-tile
static constexpr int NTILE    = N_VEC / VTILE;    // 1024

// smem layout (floats)
static constexpr int OFF_T  = 0;                  // sT  [64][512] codebook transposed
static constexpr int OFF_E  = 32768;              // sE  [512]
static constexpr int OFF_X  = 33280;              // sX  [64][128]
static constexpr int OFF_S  = 41472;              // sS  [128]
static constexpr int OFF_CD = 41600;              // sCd [128][32] candidate dists
static constexpr int OFF_CI = 45696;              // sCi [128][32] candidate idx
static constexpr int SMEM_FLOATS = 49792;
static constexpr int SMEM_BYTES  = SMEM_FLOATS * 4;   // 199168

__device__ double   g_loss = 0.0;
__device__ unsigned g_done = 0u;

// Persistent: 148 CTAs x 512 threads (16 warps/SM); CTA tile = 128 vectors x 512 codes.
// Thread tile: 8 vectors x 8 codes (32 ull accs = 64 regs), 2 passes -> 16 codes/thread.
// EXACT-INVARIANT (verified rel_err==0.0 four times, do not change):
//   d_k  = fl32( fl32(S + E_k) + (-2)*dot_k )
//   dot_k = strict sequential fp32 FMA chain over d=0..63
//   S     = 4-lane stride-4 sums combined (l0+l2)+(l1+l3)
//   argmin: strict '<', first-min in ascending k (in-thread asc k; cross-thread asc tk)
//   out   = fl(x + fl(q - x))
__global__ __launch_bounds__(THREADS, 1)
void k_main(const float* __restrict__ in, const float* __restrict__ emb,
            float* __restrict__ out, int write_extras) {
    extern __shared__ float s[];
    float* sT = s + OFF_T;
    float* sE = s + OFF_E;
    float* sX = s + OFF_X;
    float* sS = s + OFF_S;
    float* sCd = s + OFF_CD;
    int*   sCi = (int*)(s + OFF_CI);
    __shared__ double red[16];

    const int tid = threadIdx.x;
    const int tv  = tid & 15;    // vector-group 0..15 (8 vectors each)
    const int tk  = tid >> 4;    // code-group  0..31 (16 codes each)

    // ---- stage codebook TRANSPOSED ----
#pragma unroll
    for (int i = 0; i < 64; i++) {
        int lin = i * THREADS + tid;      // 0..32767
        int k = lin & 511;
        int d = lin >> 9;
        sT[d * K + k] = emb[k * D + d];
    }

    // ---- E_k: XLA 4-lane pattern, 1 code/thread ----
    {
        const int k = tid;
        const float* r = emb + k * D;
        float l0 = 0.f, l1 = 0.f, l2 = 0.f, l3 = 0.f;
#pragma unroll
        for (int i = 0; i < 16; i++) {
            l0 = __fadd_rn(l0, __fmul_rn(r[4 * i + 0], r[4 * i + 0]));
            l1 = __fadd_rn(l1, __fmul_rn(r[4 * i + 1], r[4 * i + 1]));
            l2 = __fadd_rn(l2, __fmul_rn(r[4 * i + 2], r[4 * i + 2]));
            l3 = __fadd_rn(l3, __fmul_rn(r[4 * i + 3], r[4 * i + 3]));
        }
        sE[k] = __fadd_rn(__fadd_rn(l0, l2), __fadd_rn(l1, l3));
    }
    __syncthreads();

    const ull NEG2 = dup2(-2.0f);
    double lsum = 0.0;

    for (int tile = blockIdx.x; tile < NTILE; tile += NCTA) {
        const int v0 = tile * VTILE;
        const int b  = v0 >> 12;
        const int p  = v0 & 4095;
        const float* xg = in + b * (D * HW) + p;

        // ---- stage x tile [d][128] (coalesced) ----
#pragma unroll
        for (int i = 0; i < 16; i++) {
            int lin = i * THREADS + tid;       // 0..8191
            int d   = lin >> 7;
            int vv  = lin & 127;
            sX[lin] = xg[d * HW + vv];
        }
        __syncthreads();

        // ---- S per vector (threads 0..127), exact 4-lane pattern ----
        if (tid < VTILE) {
            float l0 = 0.f, l1 = 0.f, l2 = 0.f, l3 = 0.f;
#pragma unroll
            for (int d = 0; d < 64; d += 4) {
                float x0 = sX[(d + 0) * VTILE + tid];
                float x1 = sX[(d + 1) * VTILE + tid];
                float x2 = sX[(d + 2) * VTILE + tid];
                float x3 = sX[(d + 3) * VTILE + tid];
                l0 = __fadd_rn(l0, __fmul_rn(x0, x0));
                l1 = __fadd_rn(l1, __fmul_rn(x1, x1));
                l2 = __fadd_rn(l2, __fmul_rn(x2, x2));
                l3 = __fadd_rn(l3, __fmul_rn(x3, x3));
            }
            sS[tid] = __fadd_rn(__fadd_rn(l0, l2), __fadd_rn(l1, l3));
        }
        __syncthreads();

        // ---- mainloop: 8 vec x 16 codes per thread (2 passes of 8 codes) ----
        float bestD[8];
        int   bestI[8];
#pragma unroll
        for (int j = 0; j < 8; j++) { bestD[j] = 3.4e38f; bestI[j] = 0; }

        const ull* sSp = (const ull*)(sS + tv * 8);
        ull SAB[4];
#pragma unroll
        for (int vp = 0; vp < 4; vp++) SAB[vp] = sSp[vp];

        for (int kt = 0; kt < 2; kt++) {
            const int kb = tk * 16 + kt * 8;
            ull acc[32];
#pragma unroll
            for (int i = 0; i < 32; i++) acc[i] = 0ull;

#pragma unroll 4
            for (int d = 0; d < 64; d++) {
                const float* xr = sX + d * VTILE + tv * 8;
                ulonglong2 x01 = *(const ulonglong2*)(xr);       // vec pairs (0,1),(2,3)
                ulonglong2 x23 = *(const ulonglong2*)(xr + 4);   // (4,5),(6,7)
                const float4* er = (const float4*)(sT + d * K + kb);
                float4 e0 = er[0], e1 = er[1];
                float ev[8] = { e0.x, e0.y, e0.z, e0.w, e1.x, e1.y, e1.z, e1.w };
#pragma unroll
                for (int cc = 0; cc < 8; cc++) {
                    ull ed = dup2a(ev[cc]);
                    acc[0 * 8 + cc] = fma2(x01.x, ed, acc[0 * 8 + cc]);
                    acc[1 * 8 + cc] = fma2(x01.y, ed, acc[1 * 8 + cc]);
                    acc[2 * 8 + cc] = fma2(x23.x, ed, acc[2 * 8 + cc]);
                    acc[3 * 8 + cc] = fma2(x23.y, ed, acc[3 * 8 + cc]);
                }
            }

            // epilogue: distances + running argmin (ascending k)
#pragma unroll
            for (int cc = 0; cc < 8; cc++) {
                const int kk = kb + cc;
                ull Ec = dup2a(sE[kk]);
#pragma unroll
                for (int vp = 0; vp < 4; vp++) {
                    ull t1 = add2(SAB[vp], Ec);                   // fl(S + E)
                    ull dd = fma2(acc[vp * 8 + cc], NEG2, t1);    // fl(t1 - 2*dot)
                    float d0 = ulo(dd), d1 = uhi(dd);
                    if (d0 < bestD[2 * vp])     { bestD[2 * vp] = d0;     bestI[2 * vp] = kk; }
                    if (d1 < bestD[2 * vp + 1]) { bestD[2 * vp + 1] = d1; bestI[2 * vp + 1] = kk; }
                }
            }
        }

        // ---- publish candidates [vec][tk] ----
#pragma unroll
        for (int j = 0; j < 8; j++) {
            const int vv = tv * 8 + j;
            sCd[vv * 32 + tk] = bestD[j];
            sCi[vv * 32 + tk] = bestI[j];
        }
        __syncthreads();

        // ---- final reduce (ascending tk = ascending k) + gather + store + loss ----
        if (tid < VTILE) {
            float best = 3.4e38f;
            int bi = 0;
#pragma unroll
            for (int t2 = 0; t2 < 32; t2++) {
                float dd = sCd[tid * 32 + t2];
                if (dd < best) { best = dd; bi = sCi[tid * 32 + t2]; }
            }
            float* og = out + b * (D * HW) + p + tid;
#pragma unroll
            for (int d = 0; d < 64; d++) {
                float q  = sT[d * K + bi];
                float xv = sX[d * VTILE + tid];
                float t  = __fsub_rn(q, xv);       // fl(q - x)
                og[d * HW] = __fadd_rn(xv, t);     // fl(x + (q - x))
                lsum += (double)t * (double)t;
            }
            if (write_extras) out[IDX_OFF + v0 + tid] = (float)bi;
        }
        __syncthreads();   // protect sX/sCd before next tile
    }

    // ---- loss block-reduce -> atomic; last CTA finalizes & resets globals ----
#pragma unroll
    for (int o = 16; o; o >>= 1) lsum += __shfl_down_sync(0xffffffffu, lsum, o);
    if ((tid & 31) == 0) red[tid >> 5] = lsum;
    __syncthreads();
    if (tid == 0) {
        double t = 0.0;
#pragma unroll
        for (int w = 0; w < 16; w++) t += red[w];
        atomicAdd(&g_loss, t);
        __threadfence();
        unsigned done = atomicAdd(&g_done, 1u);
        if (done == (unsigned)(gridDim.x - 1)) {
            if (write_extras)
                out[LOSS_OFF] = (float)(0.25 * g_loss / (double)N_ELEMS);
            g_loss = 0.0;
            g_done = 0u;
        }
    }
}

extern "C" void kernel_launch(void* const* d_in, const int* in_sizes, int n_in,
                              void* d_out, int out_size) {
    const float* in  = (const float*)d_in[0];
    const float* emb = (const float*)d_in[1];
    if (n_in >= 2 && in_sizes[0] == K * D && in_sizes[1] == N_ELEMS) {
        const float* t = in; in = emb; emb = t;
    }
    float* out = (float*)d_out;

    cudaFuncSetAttribute(k_main, cudaFuncAttributeMaxDynamicSharedMemorySize, SMEM_BYTES);

    const int extras = (out_size > N_ELEMS) ? 1 : 0;

    k_main<<<NCTA, THREADS, SMEM_BYTES>>>(in, emb, out, extras);
}

// round 8
// speedup vs baseline: 1.0414x; 1.0414x over previous
#include <cuda_runtime.h>
#include <cstdint>

typedef unsigned long long ull;

// ---- packed f32x2 helpers: per-lane IEEE fp32 semantics ----
__device__ __forceinline__ ull fma2(ull a, ull b, ull c) {
    ull d;
    asm("fma.rn.f32x2 %0, %1, %2, %3;" : "=l"(d) : "l"(a), "l"(b), "l"(c));
    return d;
}
__device__ __forceinline__ ull add2(ull a, ull b) {
    ull d;
    asm("add.rn.f32x2 %0, %1, %2;" : "=l"(d) : "l"(a), "l"(b));
    return d;
}
__device__ __forceinline__ float ulo(ull v) { return __uint_as_float((unsigned)v); }
__device__ __forceinline__ float uhi(ull v) { return __uint_as_float((unsigned)(v >> 32)); }
__device__ __forceinline__ ull dup2a(float x) {
    ull d;
    asm("mov.b64 %0, {%1, %1};" : "=l"(d) : "f"(x));
    return d;
}
__device__ __forceinline__ ull dup2(float x) {
    unsigned u = __float_as_uint(x);
    return ((ull)u << 32) | (ull)u;
}

static constexpr int D       = 64;
static constexpr int HW      = 4096;
static constexpr int K       = 512;
static constexpr int N_VEC   = 131072;
static constexpr int N_ELEMS = N_VEC * D;         // 8388608
static constexpr int LOSS_OFF = N_ELEMS;
static constexpr int IDX_OFF  = N_ELEMS + 1;
static constexpr int THREADS  = 512;
static constexpr int NCTA     = 148;
static constexpr int VTILE    = 64;               // vectors per CTA-tile
static constexpr int NTILE    = N_VEC / VTILE;    // 2048

// smem layout (floats)
static constexpr int OFF_T  = 0;                  // sT  [64][512] codebook transposed
static constexpr int OFF_E  = 32768;              // sE  [512]
static constexpr int OFF_X  = 33280;              // sX  [64][64]
static constexpr int OFF_S  = 37376;              // sS  [64]
static constexpr int OFF_B  = 37440;              // sB  [64] best index per vec
static constexpr int OFF_CD = 37504;              // sCd [64][32] candidate dists
static constexpr int OFF_CI = 39552;              // sCi [64][32] candidate idx
static constexpr int SMEM_FLOATS = 41600;
static constexpr int SMEM_BYTES  = SMEM_FLOATS * 4;   // 166400

__device__ double   g_loss = 0.0;
__device__ unsigned g_done = 0u;

// Persistent: 148 CTAs x 512 threads; CTA tile = 64 vectors x all 512 codes.
// Thread tile: 4 vectors x 16 codes (as 8 code-PAIRS in f32x2 lanes) -> 32 ull accs.
// Per d-iter: 1 x-LDS.128 + 4 e-LDS.128 (code-pairs, NO dup needed) + 4 dups + 32 fma2.
// EXACT-INVARIANT (verified rel_err==0.0 five times, do not change):
//   d_k  = fl32( fl32(S + E_k) + (-2)*dot_k )
//   dot_k = strict sequential fp32 FMA chain over d=0..63
//   S     = 4-lane stride-4 sums combined (l0+l2)+(l1+l3)
//   argmin: strict '<', first-min ascending k (lane0 before lane1; asc c; asc tk)
//   out   = fl(x + fl(q - x))
__global__ __launch_bounds__(THREADS, 1)
void k_main(const float* __restrict__ in, const float* __restrict__ emb,
            float* __restrict__ out, int write_extras) {
    extern __shared__ float s[];
    float* sT = s + OFF_T;
    float* sE = s + OFF_E;
    float* sX = s + OFF_X;
    float* sS = s + OFF_S;
    int*   sB = (int*)(s + OFF_B);
    float* sCd = s + OFF_CD;
    int*   sCi = (int*)(s + OFF_CI);
    __shared__ double red[16];

    const int tid = threadIdx.x;
    const int tv  = tid & 15;    // vector-group: 4 vecs [tv*4, tv*4+3]
    const int tk  = tid >> 4;    // code-group 0..31: 16 codes [tk*16, tk*16+15]

    // ---- stage codebook TRANSPOSED ----
#pragma unroll
    for (int i = 0; i < 64; i++) {
        int lin = i * THREADS + tid;      // 0..32767
        int k = lin & 511;
        int d = lin >> 9;
        sT[d * K + k] = emb[k * D + d];
    }

    // ---- E_k: XLA 4-lane pattern, 1 code/thread ----
    {
        const int k = tid;
        const float* r = emb + k * D;
        float l0 = 0.f, l1 = 0.f, l2 = 0.f, l3 = 0.f;
#pragma unroll
        for (int i = 0; i < 16; i++) {
            l0 = __fadd_rn(l0, __fmul_rn(r[4 * i + 0], r[4 * i + 0]));
            l1 = __fadd_rn(l1, __fmul_rn(r[4 * i + 1], r[4 * i + 1]));
            l2 = __fadd_rn(l2, __fmul_rn(r[4 * i + 2], r[4 * i + 2]));
            l3 = __fadd_rn(l3, __fmul_rn(r[4 * i + 3], r[4 * i + 3]));
        }
        sE[k] = __fadd_rn(__fadd_rn(l0, l2), __fadd_rn(l1, l3));
    }
    __syncthreads();

    const ull NEG2 = dup2(-2.0f);
    double lsum = 0.0;

    for (int tile = blockIdx.x; tile < NTILE; tile += NCTA) {
        const int v0 = tile * VTILE;
        const int b  = v0 >> 12;
        const int p  = v0 & 4095;
        const float* xg = in + b * (D * HW) + p;

        // ---- stage x tile [d][64] (coalesced: 8 elems/thread) ----
#pragma unroll
        for (int i = 0; i < 8; i++) {
            int lin = i * THREADS + tid;       // 0..4095
            int d   = lin >> 6;
            int vv  = lin & 63;
            sX[lin] = xg[d * HW + vv];
        }
        __syncthreads();

        // ---- S per vector (threads 0..63), exact 4-lane pattern ----
        if (tid < VTILE) {
            float l0 = 0.f, l1 = 0.f, l2 = 0.f, l3 = 0.f;
#pragma unroll
            for (int d = 0; d < 64; d += 4) {
                float x0 = sX[(d + 0) * VTILE + tid];
                float x1 = sX[(d + 1) * VTILE + tid];
                float x2 = sX[(d + 2) * VTILE + tid];
                float x3 = sX[(d + 3) * VTILE + tid];
                l0 = __fadd_rn(l0, __fmul_rn(x0, x0));
                l1 = __fadd_rn(l1, __fmul_rn(x1, x1));
                l2 = __fadd_rn(l2, __fmul_rn(x2, x2));
                l3 = __fadd_rn(l3, __fmul_rn(x3, x3));
            }
            sS[tid] = __fadd_rn(__fadd_rn(l0, l2), __fadd_rn(l1, l3));
        }
        __syncthreads();

        // ---- mainloop: 4 vec x 8 code-pairs, single k-pass ----
        ull acc[32];
#pragma unroll
        for (int i = 0; i < 32; i++) acc[i] = 0ull;

#pragma unroll 4
        for (int d = 0; d < 64; d++) {
            const float4 xv4 = *(const float4*)(sX + d * VTILE + tv * 4);  // LDS.128 dense
            const ulonglong2* er = (const ulonglong2*)(sT + d * K + tk * 16);
            ulonglong2 e0 = er[0], e1 = er[1], e2 = er[2], e3 = er[3];     // 8 code-pairs
            ull ev[8] = { e0.x, e0.y, e1.x, e1.y, e2.x, e2.y, e3.x, e3.y };
            ull x0 = dup2a(xv4.x);
            ull x1 = dup2a(xv4.y);
            ull x2 = dup2a(xv4.z);
            ull x3 = dup2a(xv4.w);
#pragma unroll
            for (int c = 0; c < 8; c++) {
                acc[0 * 8 + c] = fma2(x0, ev[c], acc[0 * 8 + c]);
                acc[1 * 8 + c] = fma2(x1, ev[c], acc[1 * 8 + c]);
                acc[2 * 8 + c] = fma2(x2, ev[c], acc[2 * 8 + c]);
                acc[3 * 8 + c] = fma2(x3, ev[c], acc[3 * 8 + c]);
            }
        }

        // ---- epilogue: distances + per-vec argmin over my 16 codes (asc k) ----
        float bestD[4];
        int   bestI[4];
#pragma unroll
        for (int vp = 0; vp < 4; vp++) { bestD[vp] = 3.4e38f; bestI[vp] = 0; }

        const float4 Sv = *(const float4*)(sS + tv * 4);
        const ull Sd[4] = { dup2(Sv.x), dup2(Sv.y), dup2(Sv.z), dup2(Sv.w) };
        const ull* ep = (const ull*)(sE + tk * 16);   // 8 E-pairs, contiguous
#pragma unroll
        for (int c = 0; c < 8; c++) {
            ull Ec = ep[c];
            const int k0 = tk * 16 + 2 * c;
#pragma unroll
            for (int vp = 0; vp < 4; vp++) {
                ull t1 = add2(Sd[vp], Ec);                 // fl(S + E) per lane
                ull dd = fma2(acc[vp * 8 + c], NEG2, t1);  // fl(t1 - 2*dot)
                float d0 = ulo(dd), d1 = uhi(dd);
                if (d0 < bestD[vp]) { bestD[vp] = d0; bestI[vp] = k0; }
                if (d1 < bestD[vp]) { bestD[vp] = d1; bestI[vp] = k0 + 1; }
            }
        }

        // ---- publish candidates [vec][tk] ----
#pragma unroll
        for (int vp = 0; vp < 4; vp++) {
            const int vv = tv * 4 + vp;
            sCd[vv * 32 + tk] = bestD[vp];
            sCi[vv * 32 + tk] = bestI[vp];
        }
        __syncthreads();

        // ---- final reduce per vec (ascending tk = ascending k) ----
        if (tid < VTILE) {
            float best = 3.4e38f;
            int bi = 0;
#pragma unroll
            for (int t2 = 0; t2 < 32; t2++) {
                float dd = sCd[tid * 32 + t2];
                if (dd < best) { best = dd; bi = sCi[tid * 32 + t2]; }
            }
            sB[tid] = bi;
            if (write_extras) out[IDX_OFF + v0 + tid] = (float)bi;
        }
        __syncthreads();

        // ---- gather + straight-through store + loss: ALL 512 threads, 8 elems each ----
        {
            const int vv = tid & 63;
            const int d0 = (tid >> 6) * 8;
            const int bi = sB[vv];
            float* og = out + b * (D * HW) + p + vv;
#pragma unroll
            for (int j = 0; j < 8; j++) {
                const int d = d0 + j;
                float q  = sT[d * K + bi];
                float xv = sX[d * VTILE + vv];
                float t  = __fsub_rn(q, xv);       // fl(q - x)
                og[d * HW] = __fadd_rn(xv, t);     // fl(x + (q - x))
                lsum += (double)t * (double)t;
            }
        }
        __syncthreads();   // protect sX/sCd/sB before next tile
    }

    // ---- loss block-reduce -> atomic; last CTA finalizes & resets globals ----
#pragma unroll
    for (int o = 16; o; o >>= 1) lsum += __shfl_down_sync(0xffffffffu, lsum, o);
    if ((tid & 31) == 0) red[tid >> 5] = lsum;
    __syncthreads();
    if (tid == 0) {
        double t = 0.0;
#pragma unroll
        for (int w = 0; w < 16; w++) t += red[w];
        atomicAdd(&g_loss, t);
        __threadfence();
        unsigned done = atomicAdd(&g_done, 1u);
        if (done == (unsigned)(gridDim.x - 1)) {
            if (write_extras)
                out[LOSS_OFF] = (float)(0.25 * g_loss / (double)N_ELEMS);
            g_loss = 0.0;
            g_done = 0u;
        }
    }
}

extern "C" void kernel_launch(void* const* d_in, const int* in_sizes, int n_in,
                              void* d_out, int out_size) {
    const float* in  = (const float*)d_in[0];
    const float* emb = (const float*)d_in[1];
    if (n_in >= 2 && in_sizes[0] == K * D && in_sizes[1] == N_ELEMS) {
        const float* t = in; in = emb; emb = t;
    }
    float* out = (float*)d_out;

    cudaFuncSetAttribute(k_main, cudaFuncAttributeMaxDynamicSharedMemorySize, SMEM_BYTES);

    const int extras = (out_size > N_ELEMS) ? 1 : 0;

    k_main<<<NCTA, THREADS, SMEM_BYTES>>>(in, emb, out, extras);
}

// round 9
// speedup vs baseline: 1.1841x; 1.1370x over previous
#include <cuda_runtime.h>
#include <cstdint>

typedef unsigned long long ull;

// ---- packed f32x2 helpers: per-lane IEEE fp32 semantics ----
__device__ __forceinline__ ull fma2(ull a, ull b, ull c) {
    ull d;
    asm("fma.rn.f32x2 %0, %1, %2, %3;" : "=l"(d) : "l"(a), "l"(b), "l"(c));
    return d;
}
__device__ __forceinline__ ull add2(ull a, ull b) {
    ull d;
    asm("add.rn.f32x2 %0, %1, %2;" : "=l"(d) : "l"(a), "l"(b));
    return d;
}
__device__ __forceinline__ float ulo(ull v) { return __uint_as_float((unsigned)v); }
__device__ __forceinline__ float uhi(ull v) { return __uint_as_float((unsigned)(v >> 32)); }
__device__ __forceinline__ ull dup2a(float x) {
    ull d;
    asm("mov.b64 %0, {%1, %1};" : "=l"(d) : "f"(x));
    return d;
}
__device__ __forceinline__ ull dup2(float x) {
    unsigned u = __float_as_uint(x);
    return ((ull)u << 32) | (ull)u;
}

static constexpr int D       = 64;
static constexpr int HW      = 4096;
static constexpr int K       = 512;
static constexpr int N_VEC   = 131072;
static constexpr int N_ELEMS = N_VEC * D;         // 8388608
static constexpr int LOSS_OFF = N_ELEMS;
static constexpr int IDX_OFF  = N_ELEMS + 1;
static constexpr int THREADS  = 512;
static constexpr int NCTA     = 148;
static constexpr int VTILE    = 128;              // vectors per CTA-tile
static constexpr int NTILE    = N_VEC / VTILE;    // 1024

// smem layout (floats)
static constexpr int OFF_T  = 0;                  // sT  [64][512] codebook transposed
static constexpr int OFF_E  = 32768;              // sE  [512]
static constexpr int OFF_X  = 33280;              // sX  [64][128]
static constexpr int OFF_S  = 41472;              // sS  [128]
static constexpr int OFF_B  = 41600;              // sB  [128]
static constexpr int OFF_CD = 41728;              // sCd [128][16]
static constexpr int OFF_CI = 43776;              // sCi [128][16]
static constexpr int SMEM_FLOATS = 45824;
static constexpr int SMEM_BYTES  = SMEM_FLOATS * 4;   // 183296

__device__ double   g_loss = 0.0;
__device__ unsigned g_done = 0u;

// Persistent: 148 CTAs x 512 threads; CTA tile = 128 vectors x all 512 codes.
// tv = tid&31 (4 vecs each, dense float4 x-loads), tk = tid>>5 (32 codes, 2 passes of 8 pairs).
// Per d-iter: 1 x-LDS.128 (dense) + 4 e-LDS.128 (full-warp broadcast) + 4 dups + 32 fma2,
// with depth-1 manual prefetch of next d's x/e.
// EXACT-INVARIANT (verified rel_err==0.0 five times, do not change):
//   d_k  = fl32( fl32(S + E_k) + (-2)*dot_k )
//   dot_k = strict sequential fp32 FMA chain over d=0..63
//   S     = 4-lane stride-4 sums combined (l0+l2)+(l1+l3)
//   argmin: strict '<', first-min ascending k (lane0<lane1; asc c; asc pass; asc tk)
//   out   = fl(x + fl(q - x))
__global__ __launch_bounds__(THREADS, 1)
void k_main(const float* __restrict__ in, const float* __restrict__ emb,
            float* __restrict__ out, int write_extras) {
    extern __shared__ float s[];
    float* sT = s + OFF_T;
    float* sE = s + OFF_E;
    float* sX = s + OFF_X;
    float* sS = s + OFF_S;
    int*   sB = (int*)(s + OFF_B);
    float* sCd = s + OFF_CD;
    int*   sCi = (int*)(s + OFF_CI);
    __shared__ double red[16];

    const int tid = threadIdx.x;
    const int tv  = tid & 31;    // vector-group: 4 vecs [tv*4, tv*4+3]
    const int tk  = tid >> 5;    // code-group 0..15: 32 codes [tk*32, tk*32+31]

    // ---- stage codebook TRANSPOSED ----
#pragma unroll
    for (int i = 0; i < 64; i++) {
        int lin = i * THREADS + tid;      // 0..32767
        int k = lin & 511;
        int d = lin >> 9;
        sT[d * K + k] = emb[k * D + d];
    }

    // ---- E_k: XLA 4-lane pattern, 1 code/thread ----
    {
        const int k = tid;
        const float* r = emb + k * D;
        float l0 = 0.f, l1 = 0.f, l2 = 0.f, l3 = 0.f;
#pragma unroll
        for (int i = 0; i < 16; i++) {
            l0 = __fadd_rn(l0, __fmul_rn(r[4 * i + 0], r[4 * i + 0]));
            l1 = __fadd_rn(l1, __fmul_rn(r[4 * i + 1], r[4 * i + 1]));
            l2 = __fadd_rn(l2, __fmul_rn(r[4 * i + 2], r[4 * i + 2]));
            l3 = __fadd_rn(l3, __fmul_rn(r[4 * i + 3], r[4 * i + 3]));
        }
        sE[k] = __fadd_rn(__fadd_rn(l0, l2), __fadd_rn(l1, l3));
    }
    __syncthreads();

    const ull NEG2 = dup2(-2.0f);
    float lsumf = 0.0f;          // fp32 loss partial (err ~1e-6 << 1e-3 tol)

    for (int tile = blockIdx.x; tile < NTILE; tile += NCTA) {
        const int v0 = tile * VTILE;
        const int b  = v0 >> 12;
        const int p  = v0 & 4095;
        const float* xg = in + b * (D * HW) + p;

        // ---- stage x tile [d][128] (coalesced) ----
#pragma unroll
        for (int i = 0; i < 16; i++) {
            int lin = i * THREADS + tid;       // 0..8191
            int d   = lin >> 7;
            int vv  = lin & 127;
            sX[lin] = xg[d * HW + vv];
        }
        __syncthreads();

        // ---- S per vector (threads 0..127), exact 4-lane pattern ----
        if (tid < VTILE) {
            float l0 = 0.f, l1 = 0.f, l2 = 0.f, l3 = 0.f;
#pragma unroll
            for (int d = 0; d < 64; d += 4) {
                float x0 = sX[(d + 0) * VTILE + tid];
                float x1 = sX[(d + 1) * VTILE + tid];
                float x2 = sX[(d + 2) * VTILE + tid];
                float x3 = sX[(d + 3) * VTILE + tid];
                l0 = __fadd_rn(l0, __fmul_rn(x0, x0));
                l1 = __fadd_rn(l1, __fmul_rn(x1, x1));
                l2 = __fadd_rn(l2, __fmul_rn(x2, x2));
                l3 = __fadd_rn(l3, __fmul_rn(x3, x3));
            }
            sS[tid] = __fadd_rn(__fadd_rn(l0, l2), __fadd_rn(l1, l3));
        }
        __syncthreads();

        // ---- per-vec running best across both k-passes ----
        float bestD[4];
        int   bestI[4];
#pragma unroll
        for (int vp = 0; vp < 4; vp++) { bestD[vp] = 3.4e38f; bestI[vp] = 0; }

        const float4 Sv = *(const float4*)(sS + tv * 4);
        const ull Sd[4] = { dup2(Sv.x), dup2(Sv.y), dup2(Sv.z), dup2(Sv.w) };

        for (int pass = 0; pass < 2; pass++) {
            const int kb = tk * 32 + pass * 16;
            ull acc[32];
#pragma unroll
            for (int i = 0; i < 32; i++) acc[i] = 0ull;

            const float* xp = sX + tv * 4;
            const float* ep = sT + kb;

            // depth-1 software pipeline (clamped next-index keeps loads in-bounds)
            float4 xv = *(const float4*)(xp);
            ulonglong2 E0 = ((const ulonglong2*)ep)[0];
            ulonglong2 E1 = ((const ulonglong2*)ep)[1];
            ulonglong2 E2 = ((const ulonglong2*)ep)[2];
            ulonglong2 E3 = ((const ulonglong2*)ep)[3];

#pragma unroll 2
            for (int d = 0; d < 64; d++) {
                const int dn = (d < 63) ? d + 1 : 63;
                const float* xq = xp + dn * VTILE;
                const ulonglong2* eq = (const ulonglong2*)(ep + dn * K);
                float4 xn = *(const float4*)(xq);
                ulonglong2 N0 = eq[0], N1 = eq[1], N2 = eq[2], N3 = eq[3];

                ull x0 = dup2a(xv.x);
                ull x1 = dup2a(xv.y);
                ull x2 = dup2a(xv.z);
                ull x3 = dup2a(xv.w);
                ull ev[8] = { E0.x, E0.y, E1.x, E1.y, E2.x, E2.y, E3.x, E3.y };
#pragma unroll
                for (int c = 0; c < 8; c++) {
                    acc[0 * 8 + c] = fma2(x0, ev[c], acc[0 * 8 + c]);
                    acc[1 * 8 + c] = fma2(x1, ev[c], acc[1 * 8 + c]);
                    acc[2 * 8 + c] = fma2(x2, ev[c], acc[2 * 8 + c]);
                    acc[3 * 8 + c] = fma2(x3, ev[c], acc[3 * 8 + c]);
                }
                xv = xn; E0 = N0; E1 = N1; E2 = N2; E3 = N3;
            }

            // epilogue: distances + running argmin (ascending k)
            const ull* epE = (const ull*)(sE + kb);   // 8 E-pairs
#pragma unroll
            for (int c = 0; c < 8; c++) {
                ull Ec = epE[c];
                const int k0 = kb + 2 * c;
#pragma unroll
                for (int vp = 0; vp < 4; vp++) {
                    ull t1 = add2(Sd[vp], Ec);                 // fl(S + E)
                    ull dd = fma2(acc[vp * 8 + c], NEG2, t1);  // fl(t1 - 2*dot)
                    float d0 = ulo(dd), d1 = uhi(dd);
                    if (d0 < bestD[vp]) { bestD[vp] = d0; bestI[vp] = k0; }
                    if (d1 < bestD[vp]) { bestD[vp] = d1; bestI[vp] = k0 + 1; }
                }
            }
        }

        // ---- publish candidates [vec][tk] ----
#pragma unroll
        for (int vp = 0; vp < 4; vp++) {
            const int vv = tv * 4 + vp;
            sCd[vv * 16 + tk] = bestD[vp];
            sCi[vv * 16 + tk] = bestI[vp];
        }
        __syncthreads();

        // ---- final reduce per vec (ascending tk = ascending k) ----
        if (tid < VTILE) {
            float best = 3.4e38f;
            int bi = 0;
#pragma unroll
            for (int t2 = 0; t2 < 16; t2++) {
                float dd = sCd[tid * 16 + t2];
                if (dd < best) { best = dd; bi = sCi[tid * 16 + t2]; }
            }
            sB[tid] = bi;
            if (write_extras) out[IDX_OFF + v0 + tid] = (float)bi;
        }
        __syncthreads();

        // ---- gather + straight-through store + loss (fp32): 16 elems/thread ----
        {
            const int vv = tid & 127;
            const int d0 = (tid >> 7) * 16;
            const int bi = sB[vv];
            float* og = out + b * (D * HW) + p + vv;
#pragma unroll
            for (int j = 0; j < 16; j++) {
                const int d = d0 + j;
                float q  = sT[d * K + bi];
                float xvv = sX[d * VTILE + vv];
                float t  = __fsub_rn(q, xvv);      // fl(q - x)
                og[d * HW] = __fadd_rn(xvv, t);    // fl(x + (q - x))
                lsumf = __fmaf_rn(t, t, lsumf);
            }
        }
        __syncthreads();   // protect sX/sCd/sB before next tile
    }

    // ---- loss block-reduce (fp32 shfl, double combine) -> one atomic/CTA ----
#pragma unroll
    for (int o = 16; o; o >>= 1) lsumf += __shfl_down_sync(0xffffffffu, lsumf, o);
    if ((tid & 31) == 0) red[tid >> 5] = (double)lsumf;
    __syncthreads();
    if (tid == 0) {
        double t = 0.0;
#pragma unroll
        for (int w = 0; w < 16; w++) t += red[w];
        atomicAdd(&g_loss, t);
        __threadfence();
        unsigned done = atomicAdd(&g_done, 1u);
        if (done == (unsigned)(gridDim.x - 1)) {
            if (write_extras)
                out[LOSS_OFF] = (float)(0.25 * g_loss / (double)N_ELEMS);
            g_loss = 0.0;
            g_done = 0u;
        }
    }
}

extern "C" void kernel_launch(void* const* d_in, const int* in_sizes, int n_in,
                              void* d_out, int out_size) {
    const float* in  = (const float*)d_in[0];
    const float* emb = (const float*)d_in[1];
    if (n_in >= 2 && in_sizes[0] == K * D && in_sizes[1] == N_ELEMS) {
        const float* t = in; in = emb; emb = t;
    }
    float* out = (float*)d_out;

    cudaFuncSetAttribute(k_main, cudaFuncAttributeMaxDynamicSharedMemorySize, SMEM_BYTES);

    const int extras = (out_size > N_ELEMS) ? 1 : 0;

    k_main<<<NCTA, THREADS, SMEM_BYTES>>>(in, emb, out, extras);
}